// round 13
// baseline (speedup 1.0000x reference)
#include <cuda_runtime.h>
#include <math.h>

#define HID 512
#define QD 32
#define OFFN 496
#define NB 296
#define NT 512

// ---------------- scratch (device globals) ----------------------------------
__device__ float d_h2[HID], d_M1[HID * QD], d_h3[HID], d_M2[HID * QD];
__device__ float d_wvec[HID], d_g2[HID], d_gvec[QD];
__device__ float d_Bo[QD * HID], d_cbo[QD];
__device__ float d_loff[OFFN], d_zow[OFFN], d_zoy[OFFN];
__device__ float d_ldiag[QD], d_zdw[QD], d_zdy[QD];

// ---------------- flat grid barriers -----------------------------------------
__device__ unsigned int g_arr[3] = {0u, 0u, 0u};
__device__ volatile unsigned int g_gen[3] = {0u, 0u, 0u};

__device__ __forceinline__ void gsync(int id) {
    __syncthreads();
    __threadfence();
    if (threadIdx.x == 0) {
        unsigned int gen = g_gen[id];
        if (atomicAdd(&g_arr[id], 1u) == NB - 1u) {
            g_arr[id] = 0u;
            __threadfence();
            g_gen[id] = gen + 1u;
        } else {
            while (g_gen[id] == gen) { }
        }
    }
    __syncthreads();
}

__device__ __forceinline__ void garrive(int id) {
    __syncthreads();
    __threadfence();
    if (threadIdx.x == 0) {
        unsigned int gen = g_gen[id];
        if (atomicAdd(&g_arr[id], 1u) == NB - 1u) {
            g_arr[id] = 0u;
            __threadfence();
            g_gen[id] = gen + 1u;
        }
    }
}

__device__ __forceinline__ float sigm(float x) { return 1.f / (1.f + expf(-x)); }

__device__ __forceinline__ float wredux(float v) {
#pragma unroll
    for (int o = 16; o; o >>= 1) v += __shfl_xor_sync(0xffffffffu, v, o);
    return v;
}

// sector-granular (32B) L2 prefetch over all later-consumed weights
__device__ __forceinline__ void pf_sector(int s,
                                          const float* __restrict__ Wo,
                                          const float* __restrict__ Wg2,
                                          const float* __restrict__ W1,
                                          const float* __restrict__ Wd,
                                          const float* __restrict__ Wg3,
                                          const float* __restrict__ Wg1) {
    const float* p;
    if (s < 31744)       p = Wo  + s * 8;
    else if (s < 64512)  p = Wg2 + (s - 31744) * 8;
    else if (s < 66560)  p = W1  + (s - 64512) * 8;
    else if (s < 68608)  p = Wd  + (s - 66560) * 8;
    else if (s < 70656)  p = Wg3 + (s - 68608) * 8;
    else                 p = Wg1 + (s - 70656) * 8;
    asm volatile("prefetch.global.L2 [%0];" :: "l"(p));
}

// warp-cooperative K=32 row pass, MLP-8. Warp w covers rows [32w, 32w+32).
__device__ __forceinline__ void rowpass32(const float* __restrict__ W,
                                          const float* __restrict__ bias,
                                          const float* __restrict__ sq4,
                                          float* __restrict__ outH,
                                          float* __restrict__ outS,
                                          int w, int lane) {
    const float4* W4 = (const float4*)W;
    const float4* q4 = (const float4*)sq4;
    float4 f[8];
#pragma unroll
    for (int k = 0; k < 8; k++)
        f[k] = __ldg(W4 + w * 256 + 32 * k + lane);
    float4 qv = q4[lane & 7];
#pragma unroll
    for (int k = 0; k < 8; k++) {
        float p = f[k].x * qv.x + f[k].y * qv.y + f[k].z * qv.z + f[k].w * qv.w;
        p += __shfl_down_sync(0xffffffffu, p, 4);
        p += __shfl_down_sync(0xffffffffu, p, 2);
        p += __shfl_down_sync(0xffffffffu, p, 1);
        if ((lane & 7) == 0) {
            int row = w * 32 + 4 * k + (lane >> 3);
            float h = sigm(p + __ldg(bias + row));
            outH[row] = h;
            if (outS) outS[row] = h * (1.f - h);
        }
    }
}

// ---------------- the one kernel ---------------------------------------------
__global__ __launch_bounds__(NT, 2)
void fused(const float* __restrict__ q, const float* __restrict__ q_t,
           const float* __restrict__ q_tt,
           const float* __restrict__ W1, const float* __restrict__ b1,
           const float* __restrict__ W2, const float* __restrict__ b2,
           const float* __restrict__ W3, const float* __restrict__ b3,
           const float* __restrict__ Wd, const float* __restrict__ bd,
           const float* __restrict__ Wo, const float* __restrict__ bo,
           const float* __restrict__ Wg1, const float* __restrict__ bg1,
           const float* __restrict__ Wg2, const float* __restrict__ bg2,
           const float* __restrict__ Wg3, const float* __restrict__ bg3,
           float* __restrict__ out) {
    __shared__ __align__(16) float shm[7424];
    int b = blockIdx.x, tid = threadIdx.x;
    int lane = tid & 31, w = tid >> 5;

    // ======== sector-granular L2 prefetch (cold-cache path; cheap) ==========
    {
        int gt = tid * NB + b;
        if (gt < 72704) pf_sector(gt, Wo, Wg2, W1, Wd, Wg3, Wg1);
    }

    // ======== Stage 0 =======================================================
    if (b < 256) {
        int rbase = b * 2;                      // 2 rows per block
        float* sW3t = shm;                      // [1024]
        float* sW2t = shm + 2048;               // [1024]
        float* sp   = shm + 4096;               // [16*2*33]
        float* sH1  = shm + 6208;
        float* sS1  = shm + 6720;
        float* sEx  = shm + 7232;
        if (tid < 256)
            ((float4*)sW2t)[tid] = __ldg((const float4*)(W2 + rbase * HID) + tid);
        else
            ((float4*)sW3t)[tid - 256] =
                __ldg((const float4*)(W3 + rbase * HID) + (tid - 256));
        if (tid < QD) { sEx[8 + tid] = __ldg(q + tid); sEx[40 + tid] = __ldg(q_t + tid); }
        __syncthreads();
        rowpass32(W1, b1, sEx + 8, sH1, sS1, w, lane);      // h1, s1 (redundant)
        __syncthreads();
        if (w < 2) {                                        // h2 rows rbase..+1
            const float4* W4 = (const float4*)(sW2t + w * HID);
            const float4* x4 = (const float4*)sH1;
            float acc = 0.f;
#pragma unroll
            for (int k = 0; k < 4; k++) {
                int i = lane + 32 * k;
                float4 a = W4[i], x = x4[i];
                acc += a.x * x.x + a.y * x.y + a.z * x.z + a.w * x.w;
            }
            acc = wredux(acc);
            if (lane == 0) {
                float h2 = sigm(acc + __ldg(b2 + rbase + w));
                d_h2[rbase + w] = h2;
                sEx[w] = h2;
            }
        }
        if (b < 32) {                                       // Bo row b, col tid
            float acc = 0.f;
#pragma unroll
            for (int i = 1; i < 32; i++)
                if (i > b)
                    acc += sEx[40 + i] *
                           __ldg(Wo + (((i * (i - 1)) >> 1) + b) * HID + tid);
            d_Bo[b * HID + tid] = acc;
        }
        if (b == 32 && tid < QD) {                          // cbo
            float acc = 0.f;
#pragma unroll
            for (int i = 1; i < 32; i++)
                if (i > tid)
                    acc += sEx[40 + i] * __ldg(bo + ((i * (i - 1)) >> 1) + tid);
            d_cbo[tid] = acc;
        }
        __syncthreads();
        {   // M1[2 rows] gemm: m = s1[c]*W1[c,:], sw = W2 tile
            const float4* sw4 = (const float4*)sW2t;
            float a0 = 0.f, a1 = 0.f;
#pragma unroll
            for (int t = 0; t < 8; t++) {
                int c4 = w * 8 + t, c = c4 * 4;
                float m0 = sS1[c + 0] * __ldg(W1 + (c + 0) * QD + lane);
                float m1 = sS1[c + 1] * __ldg(W1 + (c + 1) * QD + lane);
                float m2 = sS1[c + 2] * __ldg(W1 + (c + 2) * QD + lane);
                float m3 = sS1[c + 3] * __ldg(W1 + (c + 3) * QD + lane);
                float4 v0 = sw4[c4], v1 = sw4[128 + c4];
                a0 += v0.x * m0 + v0.y * m1 + v0.z * m2 + v0.w * m3;
                a1 += v1.x * m0 + v1.y * m1 + v1.z * m2 + v1.w * m3;
            }
            sp[(w * 2 + 0) * 33 + lane] = a0;
            sp[(w * 2 + 1) * 33 + lane] = a1;
            __syncthreads();
            if (tid < 64) {
                int i = tid >> 5, j = lane;
                float s = 0.f;
#pragma unroll
                for (int u = 0; u < 16; u++) s += sp[(u * 2 + i) * 33 + j];
                float h2 = sEx[i];
                d_M1[(rbase + i) * QD + j] = h2 * (1.f - h2) * s;
            }
        }
    } else if (b < 264) {
        // g-blocks 256..263: g1 redundant, g2 rows (b-256)*64 + w*4 .. +3
        float* sG1 = shm;            // [512]
        float* sq  = shm + 512;      // [32]
        if (tid < QD) sq[tid] = __ldg(q + tid);
        __syncthreads();
        rowpass32(Wg1, bg1, sq, sG1, nullptr, w, lane);
        __syncthreads();
        int r0 = (b - 256) * 64 + w * 4;
#pragma unroll
        for (int i = 0; i < 4; i++) {
            int r = r0 + i;
            const float4* W4 = (const float4*)(Wg2 + r * HID);
            const float4* x4 = (const float4*)sG1;
            float acc = 0.f;
#pragma unroll
            for (int k = 0; k < 4; k++) {
                int ii = lane + 32 * k;
                float4 a = __ldg(W4 + ii);
                float4 x = x4[ii];
                acc += a.x * x.x + a.y * x.y + a.z * x.z + a.w * x.w;
            }
            acc = wredux(acc);
            if (lane == 0) d_g2[r] = sigm(acc + __ldg(bg2 + r));
        }
    }
    gsync(0);

    // ======== Stage 1 =======================================================
    if (b < 256) {
        int rbase = b * 2;
        float* sW3t = shm;
        float* sH2  = shm + 2048;
        float* sp   = shm + 4096;
        float* sEx  = shm + 7232;
        if (tid < 128) ((float4*)sH2)[tid] = ((const float4*)d_h2)[tid];
        __syncthreads();
        if (w < 2) {                                        // h3 rows rbase..+1
            const float4* W4 = (const float4*)(sW3t + w * HID);
            const float4* x4 = (const float4*)sH2;
            float acc = 0.f;
#pragma unroll
            for (int k = 0; k < 4; k++) {
                int i = lane + 32 * k;
                float4 a = W4[i], x = x4[i];
                acc += a.x * x.x + a.y * x.y + a.z * x.z + a.w * x.w;
            }
            acc = wredux(acc);
            if (lane == 0) {
                float h3 = sigm(acc + __ldg(b3 + rbase + w));
                d_h3[rbase + w] = h3;
                sEx[4 + w] = h3;
            }
        }
        __syncthreads();
        {   // M2[2 rows] gemm over global M1, sw = W3 tile; epilogue: wvec
            const float* M1p = d_M1;
            const float4* sw4 = (const float4*)sW3t;
            float a0 = 0.f, a1 = 0.f;
#pragma unroll
            for (int t = 0; t < 8; t++) {
                int c4 = w * 8 + t, c = c4 * 4;
                float m0 = __ldg(M1p + (c + 0) * QD + lane);
                float m1 = __ldg(M1p + (c + 1) * QD + lane);
                float m2 = __ldg(M1p + (c + 2) * QD + lane);
                float m3 = __ldg(M1p + (c + 3) * QD + lane);
                float4 v0 = sw4[c4], v1 = sw4[128 + c4];
                a0 += v0.x * m0 + v0.y * m1 + v0.z * m2 + v0.w * m3;
                a1 += v1.x * m0 + v1.y * m1 + v1.z * m2 + v1.w * m3;
            }
            sp[(w * 2 + 0) * 33 + lane] = a0;
            sp[(w * 2 + 1) * 33 + lane] = a1;
            __syncthreads();
            if (tid < 64) {
                int i = tid >> 5, j = lane;
                float s = 0.f;
#pragma unroll
                for (int u = 0; u < 16; u++) s += sp[(u * 2 + i) * 33 + j];
                float h3 = sEx[4 + i];
                float val = h3 * (1.f - h3) * s;
                d_M2[(rbase + i) * QD + j] = val;
                float contrib = val * sEx[40 + j];
                contrib = wredux(contrib);
                if (j == 0) d_wvec[rbase + i] = contrib;
            }
        }
    } else if (b == 256) {                                  // gvec
        float* sG2 = shm;
        if (tid < 128) ((float4*)sG2)[tid] = ((const float4*)d_g2)[tid];
        __syncthreads();
#pragma unroll
        for (int i = w; i < QD; i += 16) {
            const float4* W4 = (const float4*)(Wg3 + i * HID);
            const float4* x4 = (const float4*)sG2;
            float acc = 0.f;
#pragma unroll
            for (int k = 0; k < 4; k++) {
                int ii = lane + 32 * k;
                float4 a = __ldg(W4 + ii);
                float4 x = x4[ii];
                acc += a.x * x.x + a.y * x.y + a.z * x.z + a.w * x.w;
            }
            acc = wredux(acc);
            if (lane == 0) d_gvec[i] = acc + __ldg(bg3 + i);
        }
    }
    if (b >= 33) { garrive(1); garrive(2); return; }
    gsync(1);

    // ======== Stage 2 (blocks 0..32): LTqt, y, triple-dots ==================
    {
        float* sH3 = shm;            // [512]
        float* sWv = shm + 512;      // [512]
        float* sY  = shm + 1024;     // [512]
        float* sLT = shm + 1536;     // [32]
        float* scb = shm + 1568;     // [32]
        float* sEx = shm + 7232;     // qt at +40 (b<33 wrote it in stage 0)
        if (tid < 128) {
            ((float4*)sH3)[tid] = ((const float4*)d_h3)[tid];
            ((float4*)sWv)[tid] = ((const float4*)d_wvec)[tid];
        }
        if (tid < QD) scb[tid] = d_cbo[tid];
        __syncthreads();
        // LTqt_j = exp(Wd_j.h3+bd_j)*qt_j + Bo_j.h3 + cbo_j  (2 j per warp)
#pragma unroll
        for (int jj = w; jj < QD; jj += 16) {
            const float4* A4 = (const float4*)(d_Bo + jj * HID);
            const float4* B4 = (const float4*)(Wd + jj * HID);
            const float4* x4 = (const float4*)sH3;
            float sa = 0.f, sb = 0.f;
#pragma unroll
            for (int k = 0; k < 4; k++) {
                int i = lane + 32 * k;
                float4 av = __ldg(A4 + i), bv = __ldg(B4 + i), xv = x4[i];
                sa += av.x * xv.x + av.y * xv.y + av.z * xv.z + av.w * xv.w;
                sb += bv.x * xv.x + bv.y * xv.y + bv.z * xv.z + bv.w * xv.w;
            }
#pragma unroll
            for (int o = 16; o; o >>= 1) {
                sa += __shfl_xor_sync(0xffffffffu, sa, o);
                sb += __shfl_xor_sync(0xffffffffu, sb, o);
            }
            if (lane == 0)
                sLT[jj] = expf(sb + __ldg(bd + jj)) * sEx[40 + jj] + sa + scb[jj];
        }
        __syncthreads();
        // y = M2 @ LTqt, warp-segmented (coalesced, MLP-8)
        {
            const float4* M4 = (const float4*)d_M2;
            const float4* l4 = (const float4*)sLT;
            float4 f[8];
#pragma unroll
            for (int k = 0; k < 8; k++)
                f[k] = __ldg(M4 + w * 256 + 32 * k + lane);
            float4 lv = l4[lane & 7];
#pragma unroll
            for (int k = 0; k < 8; k++) {
                float p = f[k].x * lv.x + f[k].y * lv.y + f[k].z * lv.z + f[k].w * lv.w;
                p += __shfl_down_sync(0xffffffffu, p, 4);
                p += __shfl_down_sync(0xffffffffu, p, 2);
                p += __shfl_down_sync(0xffffffffu, p, 1);
                if ((lane & 7) == 0) sY[w * 32 + 4 * k + (lane >> 3)] = p;
            }
        }
        __syncthreads();
        // triple-RHS dot: task t = b*16+w in [0,528)
        {
            int t = b * 16 + w;
            const float* Wrow = (t < OFFN) ? (Wo + t * HID)
                                           : (Wd + (t - OFFN) * HID);
            const float4* W4 = (const float4*)Wrow;
            const float4* x1 = (const float4*)sH3;
            const float4* x2 = (const float4*)sWv;
            const float4* x3 = (const float4*)sY;
            float d1 = 0.f, d2 = 0.f, d3 = 0.f;
#pragma unroll
            for (int k = 0; k < 4; k++) {
                int i = lane + 32 * k;
                float4 wv = __ldg(W4 + i);
                float4 a = x1[i], c = x2[i], e = x3[i];
                d1 += wv.x * a.x + wv.y * a.y + wv.z * a.z + wv.w * a.w;
                d2 += wv.x * c.x + wv.y * c.y + wv.z * c.z + wv.w * c.w;
                d3 += wv.x * e.x + wv.y * e.y + wv.z * e.z + wv.w * e.w;
            }
#pragma unroll
            for (int o = 16; o; o >>= 1) {
                d1 += __shfl_xor_sync(0xffffffffu, d1, o);
                d2 += __shfl_xor_sync(0xffffffffu, d2, o);
                d3 += __shfl_xor_sync(0xffffffffu, d3, o);
            }
            if (lane == 0) {
                if (t < OFFN) {
                    d_loff[t] = d1 + __ldg(bo + t);
                    d_zow[t] = d2;
                    d_zoy[t] = d3;
                } else {
                    int i = t - OFFN;
                    d_ldiag[i] = expf(d1 + __ldg(bd + i));
                    d_zdw[i] = d2;
                    d_zdy[i] = d3;
                }
            }
        }
    }
    if (b != 0) { garrive(2); return; }
    gsync(2);

    // ======== Final (block 0): tau = c1+c2 + 0.5*c3 - 0.5*c4 + g ============
    {
        float* sLo  = shm;          // [496]
        float* sLd  = shm + 496;    // [32]
        float* szow = shm + 528;    // [496]
        float* szoy = shm + 1024;   // [496]
        float* szdw = shm + 1520;   // [32]
        float* szdy = shm + 1552;   // [32]
        float* sqt  = shm + 1584;   // [32]
        float* sqtt = shm + 1616;   // [32]
        float* sgv  = shm + 1648;   // [32]
        float* sLT  = shm + 1680;   // [32]
        float* st   = shm + 1712;   // [32]
        __syncthreads();
        for (int t = tid; t < OFFN; t += NT) {
            sLo[t] = d_loff[t]; szow[t] = d_zow[t]; szoy[t] = d_zoy[t];
        }
        if (tid < QD) {
            sLd[tid] = d_ldiag[tid]; szdw[tid] = d_zdw[tid]; szdy[tid] = d_zdy[tid];
            sqt[tid] = __ldg(q_t + tid); sqtt[tid] = __ldg(q_tt + tid);
            sgv[tid] = d_gvec[tid];
        }
        __syncthreads();
        if (tid < QD) {
            int j = tid;
            float lt = sLd[j] * sqt[j];
            float u1 = sLd[j] * sqtt[j];
            float s2 = sLd[j] * szdw[j] * sqt[j];
            for (int i = j + 1; i < QD; i++) {
                int p = ((i * (i - 1)) >> 1) + j;
                lt += sLo[p] * sqt[i];
                u1 += sLo[p] * sqtt[i];
                s2 += szow[p] * sqt[i];
            }
            sLT[j] = lt;
            st[j] = u1 + s2;
        }
        __syncthreads();
        if (tid < QD) {
            int i = tid;
            float c12 = sLd[i] * st[i];
            float c3  = sLd[i] * szdw[i] * sLT[i];
            float c4  = sqt[i] * sLd[i] * szdy[i];
            for (int j = 0; j < i; j++) {
                int p = ((i * (i - 1)) >> 1) + j;
                c12 += sLo[p] * st[j];
                c3  += szow[p] * sLT[j];
            }
            for (int k = i + 1; k < QD; k++) {
                int p = ((k * (k - 1)) >> 1) + i;
                c4 += sqt[k] * szoy[p];
            }
            out[i] = c12 + 0.5f * (c3 - c4) + sgv[i];
        }
    }
}

// ---------------- launch ------------------------------------------------------
extern "C" void kernel_launch(void* const* d_in, const int* in_sizes, int n_in,
                              void* d_out, int out_size) {
    const float* q    = (const float*)d_in[0];
    const float* q_t  = (const float*)d_in[1];
    const float* q_tt = (const float*)d_in[2];
    const float* W1   = (const float*)d_in[3];
    const float* b1   = (const float*)d_in[4];
    const float* W2   = (const float*)d_in[5];
    const float* b2   = (const float*)d_in[6];
    const float* W3   = (const float*)d_in[7];
    const float* b3   = (const float*)d_in[8];
    const float* Wd   = (const float*)d_in[9];
    const float* bd   = (const float*)d_in[10];
    const float* Wo   = (const float*)d_in[11];
    const float* bo   = (const float*)d_in[12];
    const float* Wg1  = (const float*)d_in[13];
    const float* bg1  = (const float*)d_in[14];
    const float* Wg2  = (const float*)d_in[15];
    const float* bg2  = (const float*)d_in[16];
    const float* Wg3  = (const float*)d_in[17];
    const float* bg3  = (const float*)d_in[18];
    float* out = (float*)d_out;

    fused<<<NB, NT>>>(q, q_t, q_tt, W1, b1, W2, b2, W3, b3, Wd, bd, Wo, bo,
                      Wg1, bg1, Wg2, bg2, Wg3, bg3, out);
}

// round 14
// speedup vs baseline: 1.0890x; 1.0890x over previous
#include <cuda_runtime.h>
#include <math.h>

#define HID 512
#define QD 32
#define OFFN 496
#define NB 132
#define NT 512

// ---------------- scratch (device globals) ----------------------------------
__device__ float d_h2[HID], d_M1[HID * QD], d_h3[HID], d_M2[HID * QD];
__device__ float d_wvec[HID], d_g2[HID], d_gvec[QD];
__device__ float d_Bo[QD * HID], d_cbo[QD];
__device__ float d_loff[OFFN], d_zow[OFFN], d_zoy[OFFN];
__device__ float d_ldiag[QD], d_zdw[QD], d_zdy[QD];

// ---------------- flat grid barriers -----------------------------------------
__device__ unsigned int g_arr[3] = {0u, 0u, 0u};
__device__ volatile unsigned int g_gen[3] = {0u, 0u, 0u};

__device__ __forceinline__ void gsync(int id) {
    __syncthreads();
    if (threadIdx.x == 0) {
        __threadfence();
        unsigned int gen = g_gen[id];
        if (atomicAdd(&g_arr[id], 1u) == NB - 1u) {
            g_arr[id] = 0u;
            __threadfence();
            g_gen[id] = gen + 1u;
        } else {
            while (g_gen[id] == gen) { }
        }
    }
    __syncthreads();
}

__device__ __forceinline__ void garrive(int id) {
    __syncthreads();
    if (threadIdx.x == 0) {
        __threadfence();
        unsigned int gen = g_gen[id];
        if (atomicAdd(&g_arr[id], 1u) == NB - 1u) {
            g_arr[id] = 0u;
            __threadfence();
            g_gen[id] = gen + 1u;
        }
    }
}

__device__ __forceinline__ float sigm(float x) { return 1.f / (1.f + expf(-x)); }

__device__ __forceinline__ float wredux(float v) {
#pragma unroll
    for (int o = 16; o; o >>= 1) v += __shfl_xor_sync(0xffffffffu, v, o);
    return v;
}

// sector-granular (32B) L2 prefetch over all later-consumed weights
__device__ __forceinline__ void pf_sector(int s,
                                          const float* __restrict__ Wo,
                                          const float* __restrict__ Wg2,
                                          const float* __restrict__ W1,
                                          const float* __restrict__ Wd,
                                          const float* __restrict__ Wg3,
                                          const float* __restrict__ Wg1) {
    const float* p;
    if (s < 31744)       p = Wo  + s * 8;
    else if (s < 64512)  p = Wg2 + (s - 31744) * 8;
    else if (s < 66560)  p = W1  + (s - 64512) * 8;
    else if (s < 68608)  p = Wd  + (s - 66560) * 8;
    else if (s < 70656)  p = Wg3 + (s - 68608) * 8;
    else                 p = Wg1 + (s - 70656) * 8;
    asm volatile("prefetch.global.L2 [%0];" :: "l"(p));
}

// warp-cooperative K=32 row pass, MLP-8. Warp w covers rows [32w, 32w+32).
__device__ __forceinline__ void rowpass32(const float* __restrict__ W,
                                          const float* __restrict__ bias,
                                          const float* __restrict__ sq4,
                                          float* __restrict__ outH,
                                          float* __restrict__ outS,
                                          int w, int lane) {
    const float4* W4 = (const float4*)W;
    const float4* q4 = (const float4*)sq4;
    float4 f[8];
#pragma unroll
    for (int k = 0; k < 8; k++)
        f[k] = __ldg(W4 + w * 256 + 32 * k + lane);
    float4 qv = q4[lane & 7];
#pragma unroll
    for (int k = 0; k < 8; k++) {
        float p = f[k].x * qv.x + f[k].y * qv.y + f[k].z * qv.z + f[k].w * qv.w;
        p += __shfl_down_sync(0xffffffffu, p, 4);
        p += __shfl_down_sync(0xffffffffu, p, 2);
        p += __shfl_down_sync(0xffffffffu, p, 1);
        if ((lane & 7) == 0) {
            int row = w * 32 + 4 * k + (lane >> 3);
            float h = sigm(p + __ldg(bias + row));
            outH[row] = h;
            if (outS) outS[row] = h * (1.f - h);
        }
    }
}

// ---------------- the one kernel ---------------------------------------------
__global__ __launch_bounds__(NT)
void fused(const float* __restrict__ q, const float* __restrict__ q_t,
           const float* __restrict__ q_tt,
           const float* __restrict__ W1, const float* __restrict__ b1,
           const float* __restrict__ W2, const float* __restrict__ b2,
           const float* __restrict__ W3, const float* __restrict__ b3,
           const float* __restrict__ Wd, const float* __restrict__ bd,
           const float* __restrict__ Wo, const float* __restrict__ bo,
           const float* __restrict__ Wg1, const float* __restrict__ bg1,
           const float* __restrict__ Wg2, const float* __restrict__ bg2,
           const float* __restrict__ Wg3, const float* __restrict__ bg3,
           float* __restrict__ out) {
    __shared__ __align__(16) float shm[7424];
    int b = blockIdx.x, tid = threadIdx.x;
    int lane = tid & 31, w = tid >> 5;

    // ======== sector-granular L2 prefetch of all weight sectors =============
    {
        int gt = tid * NB + b;                  // unique in [0, 67584)
        pf_sector(gt, Wo, Wg2, W1, Wd, Wg3, Wg1);
        if (gt < 72704 - 67584)
            pf_sector(gt + 67584, Wo, Wg2, W1, Wd, Wg3, Wg1);
    }

    // ======== Stage 0 =======================================================
    if (b < 128) {
        int rbase = b * 4;
        float* sW3t = shm;
        float* sW2t = shm + 2048;
        float* sp   = shm + 4096;
        float* sH1  = shm + 6208;
        float* sS1  = shm + 6720;
        float* sEx  = shm + 7232;
        ((float4*)sW2t)[tid] = __ldg((const float4*)(W2 + rbase * HID) + tid);
        ((float4*)sW3t)[tid] = __ldg((const float4*)(W3 + rbase * HID) + tid);
        if (tid < QD) { sEx[8 + tid] = __ldg(q + tid); sEx[40 + tid] = __ldg(q_t + tid); }
        __syncthreads();
        rowpass32(W1, b1, sEx + 8, sH1, sS1, w, lane);      // h1, s1 (redundant)
        __syncthreads();
        if (w < 4) {                                        // h2 rows rbase..+3
            const float4* W4 = (const float4*)(sW2t + w * HID);
            const float4* x4 = (const float4*)sH1;
            float acc = 0.f;
#pragma unroll
            for (int k = 0; k < 4; k++) {
                int i = lane + 32 * k;
                float4 a = W4[i], x = x4[i];
                acc += a.x * x.x + a.y * x.y + a.z * x.z + a.w * x.w;
            }
            acc = wredux(acc);
            if (lane == 0) {
                float h2 = sigm(acc + __ldg(b2 + rbase + w));
                d_h2[rbase + w] = h2;
                sEx[w] = h2;
            }
        }
        if (b < 32) {                                       // Bo row b, col tid
            float acc = 0.f;
#pragma unroll
            for (int i = 1; i < 32; i++)
                if (i > b)
                    acc += sEx[40 + i] *
                           __ldg(Wo + (((i * (i - 1)) >> 1) + b) * HID + tid);
            d_Bo[b * HID + tid] = acc;
        }
        if (b == 32 && tid < QD) {                          // cbo
            float acc = 0.f;
#pragma unroll
            for (int i = 1; i < 32; i++)
                if (i > tid)
                    acc += sEx[40 + i] * __ldg(bo + ((i * (i - 1)) >> 1) + tid);
            d_cbo[tid] = acc;
        }
        __syncthreads();
        {   // M1[R] gemm: m = s1[c]*W1[c,:], sw = W2 tile
            const float4* sw4 = (const float4*)sW2t;
            float a0 = 0.f, a1 = 0.f, a2 = 0.f, a3 = 0.f;
#pragma unroll
            for (int t = 0; t < 8; t++) {
                int c4 = w * 8 + t, c = c4 * 4;
                float m0 = sS1[c + 0] * __ldg(W1 + (c + 0) * QD + lane);
                float m1 = sS1[c + 1] * __ldg(W1 + (c + 1) * QD + lane);
                float m2 = sS1[c + 2] * __ldg(W1 + (c + 2) * QD + lane);
                float m3 = sS1[c + 3] * __ldg(W1 + (c + 3) * QD + lane);
                float4 v0 = sw4[c4], v1 = sw4[128 + c4],
                       v2 = sw4[256 + c4], v3 = sw4[384 + c4];
                a0 += v0.x * m0 + v0.y * m1 + v0.z * m2 + v0.w * m3;
                a1 += v1.x * m0 + v1.y * m1 + v1.z * m2 + v1.w * m3;
                a2 += v2.x * m0 + v2.y * m1 + v2.z * m2 + v2.w * m3;
                a3 += v3.x * m0 + v3.y * m1 + v3.z * m2 + v3.w * m3;
            }
            sp[(w * 4 + 0) * 33 + lane] = a0;
            sp[(w * 4 + 1) * 33 + lane] = a1;
            sp[(w * 4 + 2) * 33 + lane] = a2;
            sp[(w * 4 + 3) * 33 + lane] = a3;
            __syncthreads();
            if (tid < 128) {
                int i = tid >> 5, j = lane;
                float s = 0.f;
#pragma unroll
                for (int u = 0; u < 16; u++) s += sp[(u * 4 + i) * 33 + j];
                float h2 = sEx[i];
                d_M1[(rbase + i) * QD + j] = h2 * (1.f - h2) * s;
            }
        }
    } else {
        // g-blocks 128..131: g1 redundant, g2 rows (b-128)*128 .. +127
        float* sG1 = shm;            // [512]
        float* sq  = shm + 512;      // [32]
        if (tid < QD) sq[tid] = __ldg(q + tid);
        __syncthreads();
        rowpass32(Wg1, bg1, sq, sG1, nullptr, w, lane);
        __syncthreads();
        int r0 = (b - 128) * 128 + w * 8;
#pragma unroll
        for (int i = 0; i < 8; i++) {
            int r = r0 + i;
            const float4* W4 = (const float4*)(Wg2 + r * HID);
            const float4* x4 = (const float4*)sG1;
            float acc = 0.f;
#pragma unroll
            for (int k = 0; k < 4; k++) {
                int ii = lane + 32 * k;
                float4 a = __ldg(W4 + ii);
                float4 x = x4[ii];
                acc += a.x * x.x + a.y * x.y + a.z * x.z + a.w * x.w;
            }
            acc = wredux(acc);
            if (lane == 0) d_g2[r] = sigm(acc + __ldg(bg2 + r));
        }
    }
    gsync(0);

    // ======== Stage 1 =======================================================
    if (b < 128) {
        int rbase = b * 4;
        float* sW3t = shm;
        float* sH2  = shm + 2048;
        float* sp   = shm + 4096;
        float* sEx  = shm + 7232;
        if (tid < 128) ((float4*)sH2)[tid] = ((const float4*)d_h2)[tid];
        __syncthreads();
        if (w < 4) {                                        // h3 rows rbase..+3
            const float4* W4 = (const float4*)(sW3t + w * HID);
            const float4* x4 = (const float4*)sH2;
            float acc = 0.f;
#pragma unroll
            for (int k = 0; k < 4; k++) {
                int i = lane + 32 * k;
                float4 a = W4[i], x = x4[i];
                acc += a.x * x.x + a.y * x.y + a.z * x.z + a.w * x.w;
            }
            acc = wredux(acc);
            if (lane == 0) {
                float h3 = sigm(acc + __ldg(b3 + rbase + w));
                d_h3[rbase + w] = h3;
                sEx[4 + w] = h3;
            }
        }
        __syncthreads();
        {   // M2[R] gemm over global M1, sw = W3 tile; epilogue: wvec
            const float* M1p = d_M1;
            const float4* sw4 = (const float4*)sW3t;
            float a0 = 0.f, a1 = 0.f, a2 = 0.f, a3 = 0.f;
#pragma unroll
            for (int t = 0; t < 8; t++) {
                int c4 = w * 8 + t, c = c4 * 4;
                float m0 = __ldg(M1p + (c + 0) * QD + lane);
                float m1 = __ldg(M1p + (c + 1) * QD + lane);
                float m2 = __ldg(M1p + (c + 2) * QD + lane);
                float m3 = __ldg(M1p + (c + 3) * QD + lane);
                float4 v0 = sw4[c4], v1 = sw4[128 + c4],
                       v2 = sw4[256 + c4], v3 = sw4[384 + c4];
                a0 += v0.x * m0 + v0.y * m1 + v0.z * m2 + v0.w * m3;
                a1 += v1.x * m0 + v1.y * m1 + v1.z * m2 + v1.w * m3;
                a2 += v2.x * m0 + v2.y * m1 + v2.z * m2 + v2.w * m3;
                a3 += v3.x * m0 + v3.y * m1 + v3.z * m2 + v3.w * m3;
            }
            sp[(w * 4 + 0) * 33 + lane] = a0;
            sp[(w * 4 + 1) * 33 + lane] = a1;
            sp[(w * 4 + 2) * 33 + lane] = a2;
            sp[(w * 4 + 3) * 33 + lane] = a3;
            __syncthreads();
            if (tid < 128) {
                int i = tid >> 5, j = lane;
                float s = 0.f;
#pragma unroll
                for (int u = 0; u < 16; u++) s += sp[(u * 4 + i) * 33 + j];
                float h3 = sEx[4 + i];
                float val = h3 * (1.f - h3) * s;
                d_M2[(rbase + i) * QD + j] = val;
                float contrib = val * sEx[40 + j];
                contrib = wredux(contrib);
                if (j == 0) d_wvec[rbase + i] = contrib;
            }
        }
    } else if (b == 128) {                                  // gvec
        float* sG2 = shm;
        if (tid < 128) ((float4*)sG2)[tid] = ((const float4*)d_g2)[tid];
        __syncthreads();
#pragma unroll
        for (int i = w; i < QD; i += 16) {
            const float4* W4 = (const float4*)(Wg3 + i * HID);
            const float4* x4 = (const float4*)sG2;
            float acc = 0.f;
#pragma unroll
            for (int k = 0; k < 4; k++) {
                int ii = lane + 32 * k;
                float4 a = __ldg(W4 + ii);
                float4 x = x4[ii];
                acc += a.x * x.x + a.y * x.y + a.z * x.z + a.w * x.w;
            }
            acc = wredux(acc);
            if (lane == 0) d_gvec[i] = acc + __ldg(bg3 + i);
        }
    }
    if (b >= 33) { garrive(1); garrive(2); return; }
    gsync(1);

    // ======== Stage 2 (blocks 0..32): LTqt, y, triple-dots ==================
    {
        float* sH3 = shm;            // [512]
        float* sWv = shm + 512;      // [512]
        float* sY  = shm + 1024;     // [512]
        float* sLT = shm + 1536;     // [32]
        float* scb = shm + 1568;     // [32]
        float* sEx = shm + 7232;     // qt at +40 (still valid: b<33 < 128)
        if (tid < 128) {
            ((float4*)sH3)[tid] = ((const float4*)d_h3)[tid];
            ((float4*)sWv)[tid] = ((const float4*)d_wvec)[tid];
        }
        if (tid < QD) scb[tid] = d_cbo[tid];
        __syncthreads();
        // LTqt_j = exp(Wd_j.h3+bd_j)*qt_j + Bo_j.h3 + cbo_j  (2 j per warp)
#pragma unroll
        for (int jj = w; jj < QD; jj += 16) {
            const float4* A4 = (const float4*)(d_Bo + jj * HID);
            const float4* B4 = (const float4*)(Wd + jj * HID);
            const float4* x4 = (const float4*)sH3;
            float sa = 0.f, sb = 0.f;
#pragma unroll
            for (int k = 0; k < 4; k++) {
                int i = lane + 32 * k;
                float4 av = __ldg(A4 + i), bv = __ldg(B4 + i), xv = x4[i];
                sa += av.x * xv.x + av.y * xv.y + av.z * xv.z + av.w * xv.w;
                sb += bv.x * xv.x + bv.y * xv.y + bv.z * xv.z + bv.w * xv.w;
            }
#pragma unroll
            for (int o = 16; o; o >>= 1) {
                sa += __shfl_xor_sync(0xffffffffu, sa, o);
                sb += __shfl_xor_sync(0xffffffffu, sb, o);
            }
            if (lane == 0)
                sLT[jj] = expf(sb + __ldg(bd + jj)) * sEx[40 + jj] + sa + scb[jj];
        }
        __syncthreads();
        // y = M2 @ LTqt, warp-segmented (coalesced, MLP-8)
        {
            const float4* M4 = (const float4*)d_M2;
            const float4* l4 = (const float4*)sLT;
            float4 f[8];
#pragma unroll
            for (int k = 0; k < 8; k++)
                f[k] = __ldg(M4 + w * 256 + 32 * k + lane);
            float4 lv = l4[lane & 7];
#pragma unroll
            for (int k = 0; k < 8; k++) {
                float p = f[k].x * lv.x + f[k].y * lv.y + f[k].z * lv.z + f[k].w * lv.w;
                p += __shfl_down_sync(0xffffffffu, p, 4);
                p += __shfl_down_sync(0xffffffffu, p, 2);
                p += __shfl_down_sync(0xffffffffu, p, 1);
                if ((lane & 7) == 0) sY[w * 32 + 4 * k + (lane >> 3)] = p;
            }
        }
        __syncthreads();
        // triple-RHS dot: task t = b*16+w in [0,528)
        {
            int t = b * 16 + w;
            const float* Wrow = (t < OFFN) ? (Wo + t * HID)
                                           : (Wd + (t - OFFN) * HID);
            const float4* W4 = (const float4*)Wrow;
            const float4* x1 = (const float4*)sH3;
            const float4* x2 = (const float4*)sWv;
            const float4* x3 = (const float4*)sY;
            float d1 = 0.f, d2 = 0.f, d3 = 0.f;
#pragma unroll
            for (int k = 0; k < 4; k++) {
                int i = lane + 32 * k;
                float4 wv = __ldg(W4 + i);
                float4 a = x1[i], c = x2[i], e = x3[i];
                d1 += wv.x * a.x + wv.y * a.y + wv.z * a.z + wv.w * a.w;
                d2 += wv.x * c.x + wv.y * c.y + wv.z * c.z + wv.w * c.w;
                d3 += wv.x * e.x + wv.y * e.y + wv.z * e.z + wv.w * e.w;
            }
#pragma unroll
            for (int o = 16; o; o >>= 1) {
                d1 += __shfl_xor_sync(0xffffffffu, d1, o);
                d2 += __shfl_xor_sync(0xffffffffu, d2, o);
                d3 += __shfl_xor_sync(0xffffffffu, d3, o);
            }
            if (lane == 0) {
                if (t < OFFN) {
                    d_loff[t] = d1 + __ldg(bo + t);
                    d_zow[t] = d2;
                    d_zoy[t] = d3;
                } else {
                    int i = t - OFFN;
                    d_ldiag[i] = expf(d1 + __ldg(bd + i));
                    d_zdw[i] = d2;
                    d_zdy[i] = d3;
                }
            }
        }
    }
    if (b != 0) { garrive(2); return; }
    gsync(2);

    // ======== Final (block 0): warp-parallel assembly =======================
    // tau = c1+c2 + 0.5*c3 - 0.5*c4 + g   (comp_5 == comp_3)
    {
        float* sLo  = shm;          // [496]
        float* sLd  = shm + 496;    // [32]
        float* szow = shm + 528;    // [496]
        float* szoy = shm + 1024;   // [496]
        float* szdw = shm + 1520;   // [32]
        float* szdy = shm + 1552;   // [32]
        float* sqt  = shm + 1584;   // [32]
        float* sqtt = shm + 1616;   // [32]
        float* sgv  = shm + 1648;   // [32]
        float* sLT  = shm + 1680;   // [32]
        float* sst  = shm + 1712;   // [32]
        __syncthreads();
        for (int t = tid; t < OFFN; t += NT) {
            sLo[t] = d_loff[t]; szow[t] = d_zow[t]; szoy[t] = d_zoy[t];
        }
        if (tid < QD) {
            sLd[tid] = d_ldiag[tid]; szdw[tid] = d_zdw[tid]; szdy[tid] = d_zdy[tid];
            sqt[tid] = __ldg(q_t + tid); sqtt[tid] = __ldg(q_tt + tid);
            sgv[tid] = d_gvec[tid];
        }
        __syncthreads();
        // Phase A: warp w computes LT[j], st[j] for j = w, w+16 (lane = i)
#pragma unroll
        for (int j = w; j < QD; j += 16) {
            int i = lane;
            float lt = 0.f, u1 = 0.f, s2 = 0.f;
            if (i == j) {
                lt = sLd[j] * sqt[j];
                u1 = sLd[j] * sqtt[j];
                s2 = sLd[j] * szdw[j] * sqt[j];
            } else if (i > j) {
                int p = ((i * (i - 1)) >> 1) + j;
                float lo = sLo[p];
                lt = lo * sqt[i];
                u1 = lo * sqtt[i];
                s2 = szow[p] * sqt[i];
            }
            lt = wredux(lt); u1 = wredux(u1); s2 = wredux(s2);
            if (lane == 0) { sLT[j] = lt; sst[j] = u1 + s2; }
        }
        __syncthreads();
        // Phase B: warp w computes out[i] for i = w, w+16 (lane = j)
#pragma unroll
        for (int i = w; i < QD; i += 16) {
            int j = lane;
            float c12 = 0.f, c3 = 0.f, c4 = 0.f;
            if (j == i) {
                c12 = sLd[i] * sst[i];
                c3  = sLd[i] * szdw[i] * sLT[i];
                c4  = sqt[i] * sLd[i] * szdy[i];
            } else if (j < i) {
                int p = ((i * (i - 1)) >> 1) + j;
                c12 = sLo[p] * sst[j];
                c3  = szow[p] * sLT[j];
            } else {
                int p = ((j * (j - 1)) >> 1) + i;
                c4 = sqt[j] * szoy[p];
            }
            c12 = wredux(c12); c3 = wredux(c3); c4 = wredux(c4);
            if (lane == 0) out[i] = c12 + 0.5f * (c3 - c4) + sgv[i];
        }
    }
}

// ---------------- launch ------------------------------------------------------
extern "C" void kernel_launch(void* const* d_in, const int* in_sizes, int n_in,
                              void* d_out, int out_size) {
    const float* q    = (const float*)d_in[0];
    const float* q_t  = (const float*)d_in[1];
    const float* q_tt = (const float*)d_in[2];
    const float* W1   = (const float*)d_in[3];
    const float* b1   = (const float*)d_in[4];
    const float* W2   = (const float*)d_in[5];
    const float* b2   = (const float*)d_in[6];
    const float* W3   = (const float*)d_in[7];
    const float* b3   = (const float*)d_in[8];
    const float* Wd   = (const float*)d_in[9];
    const float* bd   = (const float*)d_in[10];
    const float* Wo   = (const float*)d_in[11];
    const float* bo   = (const float*)d_in[12];
    const float* Wg1  = (const float*)d_in[13];
    const float* bg1  = (const float*)d_in[14];
    const float* Wg2  = (const float*)d_in[15];
    const float* bg2  = (const float*)d_in[16];
    const float* Wg3  = (const float*)d_in[17];
    const float* bg3  = (const float*)d_in[18];
    float* out = (float*)d_out;

    fused<<<NB, NT>>>(q, q_t, q_tt, W1, b1, W2, b2, W3, b3, Wd, bd, Wo, bo,
                      Wg1, bg1, Wg2, bg2, Wg3, bg3, out);
}